// round 16
// baseline (speedup 1.0000x reference)
#include <cuda_runtime.h>
#include <cuda_fp16.h>
#include <cstdint>

// Problem constants: B=8, C=64, H=W=256
#define NB 8
#define NC 64
#define NP 65536              // H*W
#define HW 256                // H (== W)
#define CW 16384              // C*W
#define C2ELEMS (NB*NC*NP)    // 33554432
#define SELEMS  (NB*HW*HW)    // 524288
#define EPSBN 1e-5f
#define SLOPE 0.2f

// ---------------- scratch (device globals; no allocation allowed) -------------
__device__ float g_w1f[NC];
__device__ float g_b1f;
__device__ __half g_wAh[NC*NC];   // [o][c], fp16, BN-folded
__device__ float g_bAf[NC];
__device__ __half g_wOh[NC*NC];   // [o][c], fp16, BN-folded
__device__ float g_bOf[NC];
__device__ float g_C1[NB*NP];                 // (B,H,W)  2MB (L2-resident)
__device__ __half g_C2h[C2ELEMS];             // fp16 C2 (GEMM B + residual), 67MB
__device__ __half g_S12h[SELEMS];             // S1+S2 in fp16 (k34 GEMM A), 1MB

__device__ __forceinline__ float lrelu(float y) { return y >= 0.f ? y : SLOPE * y; }

__device__ __forceinline__ void mma_f16(float acc[4],
                                        uint32_t a0, uint32_t a1, uint32_t a2, uint32_t a3,
                                        uint32_t b0, uint32_t b1) {
    asm volatile(
        "mma.sync.aligned.m16n8k16.row.col.f32.f16.f16.f32 "
        "{%0,%1,%2,%3}, {%4,%5,%6,%7}, {%8,%9}, {%0,%1,%2,%3};"
        : "+f"(acc[0]), "+f"(acc[1]), "+f"(acc[2]), "+f"(acc[3])
        : "r"(a0), "r"(a1), "r"(a2), "r"(a3), "r"(b0), "r"(b1));
}

__device__ __forceinline__ void cp_async16(void* smem_dst, const void* gsrc) {
    uint32_t s = (uint32_t)__cvta_generic_to_shared(smem_dst);
    asm volatile("cp.async.cg.shared.global [%0], [%1], 16;" :: "r"(s), "l"(gsrc));
}

__device__ __forceinline__ void ldmx4(uint32_t r[4], const __half* p) {
    uint32_t ad = (uint32_t)__cvta_generic_to_shared(p);
    asm volatile("ldmatrix.sync.aligned.m8n8.x4.shared.b16 {%0,%1,%2,%3}, [%4];"
        : "=r"(r[0]), "=r"(r[1]), "=r"(r[2]), "=r"(r[3]) : "r"(ad));
}
__device__ __forceinline__ void ldmx4t(uint32_t r[4], const __half* p) {
    uint32_t ad = (uint32_t)__cvta_generic_to_shared(p);
    asm volatile("ldmatrix.sync.aligned.m8n8.x4.trans.shared.b16 {%0,%1,%2,%3}, [%4];"
        : "=r"(r[0]), "=r"(r[1]), "=r"(r[2]), "=r"(r[3]) : "r"(ad));
}

// ---------------- K0: fold BN into conv weights; fp16-round -------------------
__global__ void k0_fold(const float* __restrict__ w1, const float* __restrict__ b1,
                        const float* __restrict__ g1, const float* __restrict__ be1,
                        const float* __restrict__ m1, const float* __restrict__ v1,
                        const float* __restrict__ wA, const float* __restrict__ bA,
                        const float* __restrict__ gA, const float* __restrict__ beA,
                        const float* __restrict__ mA, const float* __restrict__ vA,
                        const float* __restrict__ wO, const float* __restrict__ bO,
                        const float* __restrict__ gO, const float* __restrict__ beO,
                        const float* __restrict__ mO, const float* __restrict__ vO) {
    int o = threadIdx.x;  // 0..63
    float aA = gA[o] * rsqrtf(vA[o] + EPSBN);
    float aO = gO[o] * rsqrtf(vO[o] + EPSBN);
    for (int c = 0; c < NC; c++) {
        g_wAh[o*NC + c] = __float2half_rn(aA * wA[o*NC + c]);
        g_wOh[o*NC + c] = __float2half_rn(aO * wO[o*NC + c]);
    }
    g_bAf[o] = aA * (bA[o] - mA[o]) + beA[o];
    g_bOf[o] = aO * (bO[o] - mO[o]) + beO[o];
    float a1 = g1[0] * rsqrtf(v1[0] + EPSBN);
    g_w1f[o] = a1 * w1[o];
    if (o == 0) g_b1f = a1 * (b1[0] - m1[0]) + be1[0];
}

// ---------------- K1: fused C1 (fp32) + C2 conv via fp16 k16 MMA --------------
__global__ __launch_bounds__(256) void k1_c1c2(const float* __restrict__ x) {
    extern __shared__ char k1sm[];
    float* xs = (float*)k1sm;                    // [64][132]
    __half* xh = (__half*)(k1sm + 33792);        // [64][136]
    int b = blockIdx.y;
    int p0 = blockIdx.x * 128;
    int tid = threadIdx.x;

    const float* xb = x + (size_t)b * NC * NP;
    #pragma unroll
    for (int t = 0; t < 8; t++) {
        int i = tid + t*256;
        int c = i >> 5, pq = i & 31;
        float4 v = *(const float4*)(xb + (size_t)c*NP + p0 + pq*4);
        *(float4*)&xs[c*132 + pq*4] = v;
        uint2 h;
        __half2 h0 = __floats2half2_rn(v.x, v.y);
        __half2 h1 = __floats2half2_rn(v.z, v.w);
        h.x = *(uint32_t*)&h0; h.y = *(uint32_t*)&h1;
        *(uint2*)&xh[c*136 + pq*4] = h;
    }
    __syncthreads();

    if (tid < 128) {
        float s = 0.f;
        #pragma unroll
        for (int c = 0; c < NC; c++) s += g_w1f[c] * xs[c*132 + tid];
        s += g_b1f;
        g_C1[(size_t)b*NP + p0 + tid] = lrelu(s);
    }

    int lane = tid & 31, warp = tid >> 5;
    int wm = warp >> 1;
    int wn = warp & 1;
    int g = lane >> 2, tig = lane & 3;
    int r0 = wm*16 + g;
    int b_row = ((lane >> 3) & 1) * 8 + (lane & 7);
    int b_col8 = (lane >> 4) * 8;

    float acc[8][4];
    #pragma unroll
    for (int nf = 0; nf < 8; nf++)
        #pragma unroll
        for (int r = 0; r < 4; r++) acc[nf][r] = 0.f;

    #pragma unroll
    for (int kf = 0; kf < 4; kf++) {
        int kk = kf*16;
        uint32_t a0 = *(const uint32_t*)&g_wAh[r0*NC + kk + 2*tig];
        uint32_t a1 = *(const uint32_t*)&g_wAh[(r0+8)*NC + kk + 2*tig];
        uint32_t a2 = *(const uint32_t*)&g_wAh[r0*NC + kk + 2*tig + 8];
        uint32_t a3 = *(const uint32_t*)&g_wAh[(r0+8)*NC + kk + 2*tig + 8];
        #pragma unroll
        for (int nb = 0; nb < 4; nb++) {
            uint32_t bb[4];
            ldmx4t(bb, &xh[(kk + b_row)*136 + wn*64 + nb*16 + b_col8]);
            mma_f16(acc[nb*2],   a0, a1, a2, a3, bb[0], bb[1]);
            mma_f16(acc[nb*2+1], a0, a1, a2, a3, bb[2], bb[3]);
        }
    }

    int o0 = wm*16 + g, o1 = o0 + 8;
    float bo0 = g_bAf[o0], bo1 = g_bAf[o1];
    #pragma unroll
    for (int nf = 0; nf < 8; nf++) {
        int col = p0 + wn*64 + nf*8 + tig*2;
        size_t off0 = (size_t)b*NC*NP + (size_t)o0*NP + col;
        size_t off1 = (size_t)b*NC*NP + (size_t)o1*NP + col;
        *(__half2*)&g_C2h[off0] = __floats2half2_rn(lrelu(acc[nf][0] + bo0),
                                                    lrelu(acc[nf][1] + bo0));
        *(__half2*)&g_C2h[off1] = __floats2half2_rn(lrelu(acc[nf][2] + bo1),
                                                    lrelu(acc[nf][3] + bo1));
    }
}
#define K1_SMEM 51200

// ---------------- K2ab: fused Gram (hi/lo split MMA) + row softmax ------------
// Block: 16 rows x 256 cols of G for (mat, b). grid (16, NB, 2), 256 thr.
// 8 warps each own 32 cols (warp w -> cols w*32..+31). After the K loop each
// block holds complete G rows in registers -> softmax in-block -> write S only.
// G is never written to gmem. C1 (2MB) is L2-resident so B re-reads are cheap.
__global__ __launch_bounds__(256) void k2ab_gram_softmax(float* __restrict__ S1o,
                                                         float* __restrict__ S2o) {
    __shared__ __half Ahi[16][40], Alo[16][40];   // [i][k]
    __shared__ __half Bhi[32][264], Blo[32][264]; // [k][j] full 256-wide
    __shared__ float pm[16][8];                   // per-warp row partials
    int mat = blockIdx.z;
    int b = blockIdx.y;
    int i0 = blockIdx.x * 16;
    const float* A = g_C1 + (size_t)b * NP;
    int tid = threadIdx.x;
    int lane = tid & 31, warp = tid >> 5;
    int g = lane >> 2, tig = lane & 3;
    int b_row = ((lane >> 3) & 1) * 8 + (lane & 7);
    int b_col8 = (lane >> 4) * 8;

    float acc[4][4];
    #pragma unroll
    for (int nf = 0; nf < 4; nf++)
        #pragma unroll
        for (int r = 0; r < 4; r++) acc[nf][r] = 0.f;

    for (int k0 = 0; k0 < HW; k0 += 32) {
        if (k0 > 0) __syncthreads();
        if (mat == 0) {
            // A: G1 rows -> Ahi[i][k] = C1[i0+i][k0+k]. 16x32 = 128 float4, tid<128.
            if (tid < 128) {
                int r = tid >> 3, q = (tid & 7) * 4;
                float4 v = *(const float4*)&A[(size_t)(i0+r)*HW + k0 + q];
                float h0=__half2float(__float2half_rn(v.x));
                float h1=__half2float(__float2half_rn(v.y));
                float h2=__half2float(__float2half_rn(v.z));
                float h3=__half2float(__float2half_rn(v.w));
                *(__half2*)&Ahi[r][q]   = __floats2half2_rn(v.x, v.y);
                *(__half2*)&Ahi[r][q+2] = __floats2half2_rn(v.z, v.w);
                *(__half2*)&Alo[r][q]   = __floats2half2_rn(v.x-h0, v.y-h1);
                *(__half2*)&Alo[r][q+2] = __floats2half2_rn(v.z-h2, v.w-h3);
            }
            // B: Bhi[k][j] = C1[j][k0+k] (transpose scatter). 256x32 = 2048 float4.
            #pragma unroll
            for (int t = 0; t < 8; t++) {
                int idx = tid + t*256;
                int jj = idx >> 3, q = (idx & 7) * 4;
                float4 v = *(const float4*)&A[(size_t)jj*HW + k0 + q];
                float vv[4] = {v.x, v.y, v.z, v.w};
                #pragma unroll
                for (int e = 0; e < 4; e++) {
                    __half h = __float2half_rn(vv[e]);
                    Bhi[q+e][jj] = h;
                    Blo[q+e][jj] = __float2half_rn(vv[e] - __half2float(h));
                }
            }
        } else {
            // A: G2 rows -> Ahi[i][k] = C1[k0+k][i0+i] (transpose). 32x16 = 128 float4.
            if (tid < 128) {
                int kk = tid >> 2, q = (tid & 3) * 4;
                float4 v = *(const float4*)&A[(size_t)(k0+kk)*HW + i0 + q];
                float vv[4] = {v.x, v.y, v.z, v.w};
                #pragma unroll
                for (int e = 0; e < 4; e++) {
                    __half h = __float2half_rn(vv[e]);
                    Ahi[q+e][kk] = h;
                    Alo[q+e][kk] = __float2half_rn(vv[e] - __half2float(h));
                }
            }
            // B: Bhi[k][j] = C1[k0+k][j] (natural). 32x256 = 2048 float4.
            #pragma unroll
            for (int t = 0; t < 8; t++) {
                int idx = tid + t*256;
                int kk = idx >> 6, q = (idx & 63) * 4;
                float4 v = *(const float4*)&A[(size_t)(k0+kk)*HW + q];
                float h0=__half2float(__float2half_rn(v.x));
                float h1=__half2float(__float2half_rn(v.y));
                float h2=__half2float(__float2half_rn(v.z));
                float h3=__half2float(__float2half_rn(v.w));
                *(__half2*)&Bhi[kk][q]   = __floats2half2_rn(v.x, v.y);
                *(__half2*)&Bhi[kk][q+2] = __floats2half2_rn(v.z, v.w);
                *(__half2*)&Blo[kk][q]   = __floats2half2_rn(v.x-h0, v.y-h1);
                *(__half2*)&Blo[kk][q+2] = __floats2half2_rn(v.z-h2, v.w-h3);
            }
        }
        __syncthreads();

        #pragma unroll
        for (int kf = 0; kf < 2; kf++) {
            int kk = kf*16;
            uint32_t ah0 = *(const uint32_t*)&Ahi[g][kk + 2*tig];
            uint32_t ah1 = *(const uint32_t*)&Ahi[g+8][kk + 2*tig];
            uint32_t ah2 = *(const uint32_t*)&Ahi[g][kk + 2*tig + 8];
            uint32_t ah3 = *(const uint32_t*)&Ahi[g+8][kk + 2*tig + 8];
            uint32_t al0 = *(const uint32_t*)&Alo[g][kk + 2*tig];
            uint32_t al1 = *(const uint32_t*)&Alo[g+8][kk + 2*tig];
            uint32_t al2 = *(const uint32_t*)&Alo[g][kk + 2*tig + 8];
            uint32_t al3 = *(const uint32_t*)&Alo[g+8][kk + 2*tig + 8];
            #pragma unroll
            for (int nb = 0; nb < 2; nb++) {
                uint32_t bh[4], bl[4];
                ldmx4t(bh, &Bhi[kk + b_row][warp*32 + nb*16 + b_col8]);
                ldmx4t(bl, &Blo[kk + b_row][warp*32 + nb*16 + b_col8]);
                mma_f16(acc[nb*2],   ah0, ah1, ah2, ah3, bh[0], bh[1]);
                mma_f16(acc[nb*2],   ah0, ah1, ah2, ah3, bl[0], bl[1]);
                mma_f16(acc[nb*2],   al0, al1, al2, al3, bh[0], bh[1]);
                mma_f16(acc[nb*2+1], ah0, ah1, ah2, ah3, bh[2], bh[3]);
                mma_f16(acc[nb*2+1], ah0, ah1, ah2, ah3, bl[2], bl[3]);
                mma_f16(acc[nb*2+1], al0, al1, al2, al3, bh[2], bh[3]);
            }
        }
    }
    __syncthreads();

    // ---- softmax over full rows (rows g and g+8 per lane group) ----
    // per-lane partial max over its 8 cols per row
    float m0 = acc[0][0], m1 = acc[0][2];
    #pragma unroll
    for (int nf = 0; nf < 4; nf++) {
        m0 = fmaxf(m0, fmaxf(acc[nf][0], acc[nf][1]));
        m1 = fmaxf(m1, fmaxf(acc[nf][2], acc[nf][3]));
    }
    #pragma unroll
    for (int o = 1; o <= 2; o <<= 1) {
        m0 = fmaxf(m0, __shfl_xor_sync(0xffffffffu, m0, o));
        m1 = fmaxf(m1, __shfl_xor_sync(0xffffffffu, m1, o));
    }
    if (tig == 0) { pm[g][warp] = m0; pm[g+8][warp] = m1; }
    __syncthreads();
    float gm0 = pm[g][0], gm1 = pm[g+8][0];
    #pragma unroll
    for (int w = 1; w < 8; w++) {
        gm0 = fmaxf(gm0, pm[g][w]);
        gm1 = fmaxf(gm1, pm[g+8][w]);
    }
    __syncthreads();
    float e[4][4];
    float s0 = 0.f, s1 = 0.f;
    #pragma unroll
    for (int nf = 0; nf < 4; nf++) {
        e[nf][0] = expf(acc[nf][0] - gm0); e[nf][1] = expf(acc[nf][1] - gm0);
        e[nf][2] = expf(acc[nf][2] - gm1); e[nf][3] = expf(acc[nf][3] - gm1);
        s0 += e[nf][0] + e[nf][1];
        s1 += e[nf][2] + e[nf][3];
    }
    #pragma unroll
    for (int o = 1; o <= 2; o <<= 1) {
        s0 += __shfl_xor_sync(0xffffffffu, s0, o);
        s1 += __shfl_xor_sync(0xffffffffu, s1, o);
    }
    if (tig == 0) { pm[g][warp] = s0; pm[g+8][warp] = s1; }
    __syncthreads();
    float gs0 = 0.f, gs1 = 0.f;
    #pragma unroll
    for (int w = 0; w < 8; w++) { gs0 += pm[g][w]; gs1 += pm[g+8][w]; }
    float inv0 = 1.f / gs0, inv1 = 1.f / gs1;

    float* dst = (mat == 0 ? S1o : S2o) + ((size_t)b*HW + i0)*HW;
    #pragma unroll
    for (int nf = 0; nf < 4; nf++) {
        int col = warp*32 + nf*8 + tig*2;
        float2 v0; v0.x = e[nf][0]*inv0; v0.y = e[nf][1]*inv0;
        float2 v1; v1.x = e[nf][2]*inv1; v1.y = e[nf][3]*inv1;
        *(float2*)&dst[(size_t)g*HW + col] = v0;
        *(float2*)&dst[(size_t)(g+8)*HW + col] = v1;
    }
}

// ---------------- K2c: S12h = fp16(S1 + S2) ------------------------------------
__global__ __launch_bounds__(256) void k2c_s12(const float* __restrict__ S1o,
                                               const float* __restrict__ S2o) {
    size_t i = ((size_t)blockIdx.x * 256 + threadIdx.x) * 8;
    float4 a0 = *(const float4*)&S1o[i];
    float4 a1 = *(const float4*)&S1o[i+4];
    float4 b0 = *(const float4*)&S2o[i];
    float4 b1 = *(const float4*)&S2o[i+4];
    __half2 h[4];
    h[0] = __floats2half2_rn(a0.x + b0.x, a0.y + b0.y);
    h[1] = __floats2half2_rn(a0.z + b0.z, a0.w + b0.w);
    h[2] = __floats2half2_rn(a1.x + b1.x, a1.y + b1.y);
    h[3] = __floats2half2_rn(a1.z + b1.z, a1.w + b1.w);
    *(uint4*)&g_S12h[i] = *(uint4*)h;
}

// ---------------- K34: fused GEMM (fp16 HMMA) + conv + smem residual ----------
__global__ __launch_bounds__(256) void k34_fused(float* __restrict__ out) {
    extern __shared__ char sm_raw[];
    __half* ring = (__half*)sm_raw;              // A stages: 2 x 10240 halves
    __half* Ball = (__half*)(sm_raw + 40960);    // [256][72]
    __half* ms = (__half*)sm_raw;                // [64][264], aliases A ring
    const int ASTG = 10240;
    int b = blockIdx.z;
    int n0 = blockIdx.x * 64;
    const __half* Ag = g_S12h + (size_t)b * HW * HW;
    const __half* Bg = g_C2h + (size_t)b * NC * NP;
    int tid = threadIdx.x;
    int lane = tid & 31;
    int warp = tid >> 5;
    int g = lane >> 2, tig = lane & 3;

    int arow[4], aq[4];
    #pragma unroll
    for (int t = 0; t < 4; t++) { int idx = tid + t*256; arow[t] = idx >> 2; aq[t] = (idx & 3) * 8; }
    int brow = tid >> 3, bq = (tid & 7) * 8;

    int a_row = warp*32 + (lane & 15);
    int a_col8 = (lane >> 4) * 8;
    int b_row = ((lane >> 3) & 1) * 8 + (lane & 7);
    int b_col8 = (lane >> 4) * 8;

    {
        __half* Ad = ring;
        #pragma unroll
        for (int t = 0; t < 4; t++)
            cp_async16(&Ad[arow[t]*40 + aq[t]], &Ag[(size_t)arow[t]*HW + aq[t]]);
        cp_async16(&Ball[brow*72 + bq], &Bg[(size_t)brow*CW + n0 + bq]);
        asm volatile("cp.async.commit_group;");
    }

    float acc[2][8][4];
    #pragma unroll
    for (int mf = 0; mf < 2; mf++)
        #pragma unroll
        for (int nf = 0; nf < 8; nf++)
            #pragma unroll
            for (int r = 0; r < 4; r++) acc[mf][nf][r] = 0.f;

    for (int k0 = 0; k0 < HW; k0 += 32) {
        int stg = (k0 >> 5) & 1;
        if (k0 + 32 < HW) {
            __half* Ad = ring + (stg^1)*ASTG;
            int kn = k0 + 32;
            #pragma unroll
            for (int t = 0; t < 4; t++)
                cp_async16(&Ad[arow[t]*40 + aq[t]], &Ag[(size_t)arow[t]*HW + kn + aq[t]]);
            cp_async16(&Ball[(kn + brow)*72 + bq], &Bg[(size_t)(kn+brow)*CW + n0 + bq]);
            asm volatile("cp.async.commit_group;");
            asm volatile("cp.async.wait_group 1;");
        } else {
            asm volatile("cp.async.wait_group 0;");
        }
        __syncthreads();

        const __half* As = ring + stg*ASTG;
        const __half* Bs = Ball + k0*72;

        #pragma unroll
        for (int kf = 0; kf < 2; kf++) {
            uint32_t a[2][4];
            #pragma unroll
            for (int mf = 0; mf < 2; mf++)
                ldmx4(a[mf], &As[(a_row + mf*16)*40 + kf*16 + a_col8]);
            #pragma unroll
            for (int nb = 0; nb < 4; nb++) {
                uint32_t bb[4];
                ldmx4t(bb, &Bs[(kf*16 + b_row)*72 + nb*16 + b_col8]);
                #pragma unroll
                for (int mf = 0; mf < 2; mf++) {
                    mma_f16(acc[mf][nb*2],   a[mf][0], a[mf][1], a[mf][2], a[mf][3], bb[0], bb[1]);
                    mma_f16(acc[mf][nb*2+1], a[mf][0], a[mf][1], a[mf][2], a[mf][3], bb[2], bb[3]);
                }
            }
        }
        __syncthreads();
    }

    #pragma unroll
    for (int mf = 0; mf < 2; mf++) {
        #pragma unroll
        for (int nf = 0; nf < 8; nf++) {
            int row0 = warp*32 + mf*16 + g;
            int row1 = row0 + 8;
            int col  = nf*8 + tig*2;
            int c0 = row0 >> 2, hh0 = row0 & 3;
            int c1 = row1 >> 2, hh1 = row1 & 3;
            *(__half2*)&ms[c0*264 + hh0*64 + col] = __floats2half2_rn(acc[mf][nf][0], acc[mf][nf][1]);
            *(__half2*)&ms[c1*264 + hh1*64 + col] = __floats2half2_rn(acc[mf][nf][2], acc[mf][nf][3]);
        }
    }
    __syncthreads();

    int wm = warp >> 1;
    int wn = warp & 1;
    int r0 = wm*16 + g;
    int o0 = r0, o1 = r0 + 8;
    float bo0 = g_bOf[o0], bo1 = g_bOf[o1];
    size_t bofs = (size_t)b * NC * NP;

    #pragma unroll
    for (int ph = 0; ph < 2; ph++) {
        int pix_base = ph*128 + wn*64;
        float acc2[8][4];
        #pragma unroll
        for (int nf = 0; nf < 8; nf++)
            #pragma unroll
            for (int r = 0; r < 4; r++) acc2[nf][r] = 0.f;

        #pragma unroll
        for (int kf = 0; kf < 4; kf++) {
            int kk = kf*16;
            uint32_t a0 = *(const uint32_t*)&g_wOh[r0*NC + kk + 2*tig];
            uint32_t a1 = *(const uint32_t*)&g_wOh[(r0+8)*NC + kk + 2*tig];
            uint32_t a2 = *(const uint32_t*)&g_wOh[r0*NC + kk + 2*tig + 8];
            uint32_t a3 = *(const uint32_t*)&g_wOh[(r0+8)*NC + kk + 2*tig + 8];
            #pragma unroll
            for (int nb = 0; nb < 4; nb++) {
                uint32_t bb[4];
                ldmx4t(bb, &ms[(kk + b_row)*264 + pix_base + nb*16 + b_col8]);
                mma_f16(acc2[nb*2],   a0, a1, a2, a3, bb[0], bb[1]);
                mma_f16(acc2[nb*2+1], a0, a1, a2, a3, bb[2], bb[3]);
            }
        }

        #pragma unroll
        for (int nf = 0; nf < 8; nf++) {
            int pix = pix_base + nf*8 + tig*2;
            int hh = pix >> 6, wl = pix & 63;
            size_t off0 = bofs + (size_t)(o0*4 + hh)*CW + n0 + wl;
            size_t off1 = bofs + (size_t)(o1*4 + hh)*CW + n0 + wl;
            float2 c20 = __half22float2(*(const __half2*)&Ball[(o0*4 + hh)*72 + wl]);
            float2 c21 = __half22float2(*(const __half2*)&Ball[(o1*4 + hh)*72 + wl]);
            float2 v0, v1;
            v0.x = c20.x + lrelu(acc2[nf][0] + bo0);
            v0.y = c20.y + lrelu(acc2[nf][1] + bo0);
            v1.x = c21.x + lrelu(acc2[nf][2] + bo1);
            v1.y = c21.y + lrelu(acc2[nf][3] + bo1);
            *(float2*)&out[off0] = v0;
            *(float2*)&out[off1] = v1;
        }
    }
}

#define K34_SMEM 77824

// ---------------- launch --------------------------------------------------------
extern "C" void kernel_launch(void* const* d_in, const int* in_sizes, int n_in,
                              void* d_out, int out_size) {
    const float* x   = (const float*)d_in[0];
    const float* w1  = (const float*)d_in[1];
    const float* b1  = (const float*)d_in[2];
    const float* g1  = (const float*)d_in[3];
    const float* be1 = (const float*)d_in[4];
    const float* m1  = (const float*)d_in[5];
    const float* v1  = (const float*)d_in[6];
    const float* wA  = (const float*)d_in[7];
    const float* bA  = (const float*)d_in[8];
    const float* gA  = (const float*)d_in[9];
    const float* beA = (const float*)d_in[10];
    const float* mA  = (const float*)d_in[11];
    const float* vA  = (const float*)d_in[12];
    const float* wO  = (const float*)d_in[13];
    const float* bO  = (const float*)d_in[14];
    const float* gO  = (const float*)d_in[15];
    const float* beO = (const float*)d_in[16];
    const float* mO  = (const float*)d_in[17];
    const float* vO  = (const float*)d_in[18];

    float* out = (float*)d_out;
    float* S1o = out + (size_t)C2ELEMS;
    float* S2o = S1o + (size_t)SELEMS;

    cudaFuncSetAttribute(k1_c1c2, cudaFuncAttributeMaxDynamicSharedMemorySize, K1_SMEM);
    cudaFuncSetAttribute(k34_fused, cudaFuncAttributeMaxDynamicSharedMemorySize, K34_SMEM);

    k0_fold<<<1, 64>>>(w1,b1,g1,be1,m1,v1, wA,bA,gA,beA,mA,vA, wO,bO,gO,beO,mO,vO);
    k1_c1c2<<<dim3(NP/128, NB), 256, K1_SMEM>>>(x);
    k2ab_gram_softmax<<<dim3(16, NB, 2), 256>>>(S1o, S2o);
    k2c_s12<<<SELEMS/(256*8), 256>>>(S1o, S2o);
    k34_fused<<<dim3(CW/64, 1, NB), 256, K34_SMEM>>>(out);
}

// round 17
// speedup vs baseline: 1.0406x; 1.0406x over previous
#include <cuda_runtime.h>
#include <cuda_fp16.h>
#include <cstdint>

// Problem constants: B=8, C=64, H=W=256
#define NB 8
#define NC 64
#define NP 65536              // H*W
#define HW 256                // H (== W)
#define CW 16384              // C*W
#define C2ELEMS (NB*NC*NP)    // 33554432
#define SELEMS  (NB*HW*HW)    // 524288
#define EPSBN 1e-5f
#define SLOPE 0.2f

// ---------------- scratch (device globals; no allocation allowed) -------------
__device__ float g_w1f[NC];
__device__ float g_b1f;
__device__ __half g_wAh[NC*NC];   // [o][c], fp16, BN-folded
__device__ float g_bAf[NC];
__device__ __half g_wOh[NC*NC];   // [o][c], fp16, BN-folded
__device__ float g_bOf[NC];
__device__ float g_C1[NB*NP];                 // (B,H,W)  2MB (L2-resident)
__device__ __half g_C2h[C2ELEMS];             // fp16 C2 (GEMM B + residual), 67MB
__device__ float g_G[2*NB*HW*HW];             // gram matrices, 4MB (L2-resident)
__device__ __half g_S12h[SELEMS];             // S1+S2 in fp16 (k34 GEMM A), 1MB

__device__ __forceinline__ float lrelu(float y) { return y >= 0.f ? y : SLOPE * y; }

__device__ __forceinline__ void mma_f16(float acc[4],
                                        uint32_t a0, uint32_t a1, uint32_t a2, uint32_t a3,
                                        uint32_t b0, uint32_t b1) {
    asm volatile(
        "mma.sync.aligned.m16n8k16.row.col.f32.f16.f16.f32 "
        "{%0,%1,%2,%3}, {%4,%5,%6,%7}, {%8,%9}, {%0,%1,%2,%3};"
        : "+f"(acc[0]), "+f"(acc[1]), "+f"(acc[2]), "+f"(acc[3])
        : "r"(a0), "r"(a1), "r"(a2), "r"(a3), "r"(b0), "r"(b1));
}

__device__ __forceinline__ void cp_async16(void* smem_dst, const void* gsrc) {
    uint32_t s = (uint32_t)__cvta_generic_to_shared(smem_dst);
    asm volatile("cp.async.cg.shared.global [%0], [%1], 16;" :: "r"(s), "l"(gsrc));
}

__device__ __forceinline__ void ldmx4(uint32_t r[4], const __half* p) {
    uint32_t ad = (uint32_t)__cvta_generic_to_shared(p);
    asm volatile("ldmatrix.sync.aligned.m8n8.x4.shared.b16 {%0,%1,%2,%3}, [%4];"
        : "=r"(r[0]), "=r"(r[1]), "=r"(r[2]), "=r"(r[3]) : "r"(ad));
}
__device__ __forceinline__ void ldmx4t(uint32_t r[4], const __half* p) {
    uint32_t ad = (uint32_t)__cvta_generic_to_shared(p);
    asm volatile("ldmatrix.sync.aligned.m8n8.x4.trans.shared.b16 {%0,%1,%2,%3}, [%4];"
        : "=r"(r[0]), "=r"(r[1]), "=r"(r[2]), "=r"(r[3]) : "r"(ad));
}

// ---------------- K0: fold BN into conv weights; fp16-round -------------------
__global__ void k0_fold(const float* __restrict__ w1, const float* __restrict__ b1,
                        const float* __restrict__ g1, const float* __restrict__ be1,
                        const float* __restrict__ m1, const float* __restrict__ v1,
                        const float* __restrict__ wA, const float* __restrict__ bA,
                        const float* __restrict__ gA, const float* __restrict__ beA,
                        const float* __restrict__ mA, const float* __restrict__ vA,
                        const float* __restrict__ wO, const float* __restrict__ bO,
                        const float* __restrict__ gO, const float* __restrict__ beO,
                        const float* __restrict__ mO, const float* __restrict__ vO) {
    int o = threadIdx.x;  // 0..63
    float aA = gA[o] * rsqrtf(vA[o] + EPSBN);
    float aO = gO[o] * rsqrtf(vO[o] + EPSBN);
    for (int c = 0; c < NC; c++) {
        g_wAh[o*NC + c] = __float2half_rn(aA * wA[o*NC + c]);
        g_wOh[o*NC + c] = __float2half_rn(aO * wO[o*NC + c]);
    }
    g_bAf[o] = aA * (bA[o] - mA[o]) + beA[o];
    g_bOf[o] = aO * (bO[o] - mO[o]) + beO[o];
    float a1 = g1[0] * rsqrtf(v1[0] + EPSBN);
    g_w1f[o] = a1 * w1[o];
    if (o == 0) g_b1f = a1 * (b1[0] - m1[0]) + be1[0];
}

// ---------------- K1: fused C1 (hi+lo exact) + C2 conv via fp16 k16 MMA -------
// smem: xh[64][136] fp16 hi (17408B) + xl[64][136] fp16 lo (17408B) = 34816B.
// C1 = sum w1*(hi+lo): error ~2^-22 per element. Conv uses hi only (== R15).
__global__ __launch_bounds__(256) void k1_c1c2(const float* __restrict__ x) {
    extern __shared__ char k1sm[];
    __half* xh = (__half*)k1sm;                  // [64][136]
    __half* xl = (__half*)(k1sm + 17408);        // [64][136]
    int b = blockIdx.y;
    int p0 = blockIdx.x * 128;
    int tid = threadIdx.x;

    const float* xb = x + (size_t)b * NC * NP;
    #pragma unroll
    for (int t = 0; t < 8; t++) {
        int i = tid + t*256;
        int c = i >> 5, pq = i & 31;
        float4 v = *(const float4*)(xb + (size_t)c*NP + p0 + pq*4);
        __half2 h0 = __floats2half2_rn(v.x, v.y);
        __half2 h1 = __floats2half2_rn(v.z, v.w);
        uint2 hh; hh.x = *(uint32_t*)&h0; hh.y = *(uint32_t*)&h1;
        *(uint2*)&xh[c*136 + pq*4] = hh;
        __half2 l0 = __floats2half2_rn(v.x - __half2float(__low2half(h0)),
                                       v.y - __half2float(__high2half(h0)));
        __half2 l1 = __floats2half2_rn(v.z - __half2float(__low2half(h1)),
                                       v.w - __half2float(__high2half(h1)));
        uint2 ll; ll.x = *(uint32_t*)&l0; ll.y = *(uint32_t*)&l1;
        *(uint2*)&xl[c*136 + pq*4] = ll;
    }
    __syncthreads();

    // C1 from hi+lo (exact to ~2^-22), fp32 accumulation
    if (tid < 128) {
        float s = 0.f;
        #pragma unroll
        for (int c = 0; c < NC; c++)
            s += g_w1f[c] * (__half2float(xh[c*136 + tid]) + __half2float(xl[c*136 + tid]));
        s += g_b1f;
        g_C1[(size_t)b*NP + p0 + tid] = lrelu(s);
    }

    int lane = tid & 31, warp = tid >> 5;
    int wm = warp >> 1;
    int wn = warp & 1;
    int g = lane >> 2, tig = lane & 3;
    int r0 = wm*16 + g;
    int b_row = ((lane >> 3) & 1) * 8 + (lane & 7);
    int b_col8 = (lane >> 4) * 8;

    float acc[8][4];
    #pragma unroll
    for (int nf = 0; nf < 8; nf++)
        #pragma unroll
        for (int r = 0; r < 4; r++) acc[nf][r] = 0.f;

    #pragma unroll
    for (int kf = 0; kf < 4; kf++) {
        int kk = kf*16;
        uint32_t a0 = *(const uint32_t*)&g_wAh[r0*NC + kk + 2*tig];
        uint32_t a1 = *(const uint32_t*)&g_wAh[(r0+8)*NC + kk + 2*tig];
        uint32_t a2 = *(const uint32_t*)&g_wAh[r0*NC + kk + 2*tig + 8];
        uint32_t a3 = *(const uint32_t*)&g_wAh[(r0+8)*NC + kk + 2*tig + 8];
        #pragma unroll
        for (int nb = 0; nb < 4; nb++) {
            uint32_t bb[4];
            ldmx4t(bb, &xh[(kk + b_row)*136 + wn*64 + nb*16 + b_col8]);
            mma_f16(acc[nb*2],   a0, a1, a2, a3, bb[0], bb[1]);
            mma_f16(acc[nb*2+1], a0, a1, a2, a3, bb[2], bb[3]);
        }
    }

    int o0 = wm*16 + g, o1 = o0 + 8;
    float bo0 = g_bAf[o0], bo1 = g_bAf[o1];
    #pragma unroll
    for (int nf = 0; nf < 8; nf++) {
        int col = p0 + wn*64 + nf*8 + tig*2;
        size_t off0 = (size_t)b*NC*NP + (size_t)o0*NP + col;
        size_t off1 = (size_t)b*NC*NP + (size_t)o1*NP + col;
        *(__half2*)&g_C2h[off0] = __floats2half2_rn(lrelu(acc[nf][0] + bo0),
                                                    lrelu(acc[nf][1] + bo0));
        *(__half2*)&g_C2h[off1] = __floats2half2_rn(lrelu(acc[nf][2] + bo1),
                                                    lrelu(acc[nf][3] + bo1));
    }
}
#define K1_SMEM 34816

// ---------------- K2a: Gram via fp16 hi/lo split tensor MMA (R15 version) -----
__global__ __launch_bounds__(256) void k2a_gram_tc() {
    __shared__ __half Ahi[64][40], Alo[64][40];   // [i][k]
    __shared__ __half Bhi[32][72], Blo[32][72];   // [k][j]
    int mat = blockIdx.z & 1;
    int b = blockIdx.z >> 1;
    int j0 = blockIdx.x * 64;
    int i0 = blockIdx.y * 64;
    const float* A = g_C1 + (size_t)b * NP;
    int tid = threadIdx.x;
    int lane = tid & 31, warp = tid >> 5;
    int wm = warp >> 1, wn = warp & 1;
    int g = lane >> 2, tig = lane & 3;
    int r0 = wm*16 + g;
    int b_row = ((lane >> 3) & 1) * 8 + (lane & 7);
    int b_col8 = (lane >> 4) * 8;

    float acc[4][4];
    #pragma unroll
    for (int nf = 0; nf < 4; nf++)
        #pragma unroll
        for (int r = 0; r < 4; r++) acc[nf][r] = 0.f;

    for (int k0 = 0; k0 < HW; k0 += 32) {
        if (k0 > 0) __syncthreads();
        if (mat == 0) {
            #pragma unroll
            for (int t = 0; t < 2; t++) {
                int idx = tid + t*256;
                int r = idx >> 3, q = (idx & 7) * 4;
                float4 v = *(const float4*)&A[(size_t)(i0+r)*HW + k0 + q];
                float h0=__half2float(__float2half_rn(v.x));
                float h1=__half2float(__float2half_rn(v.y));
                float h2=__half2float(__float2half_rn(v.z));
                float h3=__half2float(__float2half_rn(v.w));
                *(__half2*)&Ahi[r][q]   = __floats2half2_rn(v.x, v.y);
                *(__half2*)&Ahi[r][q+2] = __floats2half2_rn(v.z, v.w);
                *(__half2*)&Alo[r][q]   = __floats2half2_rn(v.x-h0, v.y-h1);
                *(__half2*)&Alo[r][q+2] = __floats2half2_rn(v.z-h2, v.w-h3);
            }
            #pragma unroll
            for (int t = 0; t < 2; t++) {
                int idx = tid + t*256;
                int jj = idx >> 3, q = (idx & 7) * 4;
                float4 v = *(const float4*)&A[(size_t)(j0+jj)*HW + k0 + q];
                float vv[4] = {v.x, v.y, v.z, v.w};
                #pragma unroll
                for (int e = 0; e < 4; e++) {
                    __half h = __float2half_rn(vv[e]);
                    Bhi[q+e][jj] = h;
                    Blo[q+e][jj] = __float2half_rn(vv[e] - __half2float(h));
                }
            }
        } else {
            #pragma unroll
            for (int t = 0; t < 2; t++) {
                int idx = tid + t*256;
                int kk = idx >> 4, q = (idx & 15) * 4;
                float4 v = *(const float4*)&A[(size_t)(k0+kk)*HW + i0 + q];
                float vv[4] = {v.x, v.y, v.z, v.w};
                #pragma unroll
                for (int e = 0; e < 4; e++) {
                    __half h = __float2half_rn(vv[e]);
                    Ahi[q+e][kk] = h;
                    Alo[q+e][kk] = __float2half_rn(vv[e] - __half2float(h));
                }
            }
            #pragma unroll
            for (int t = 0; t < 2; t++) {
                int idx = tid + t*256;
                int kk = idx >> 4, q = (idx & 15) * 4;
                float4 v = *(const float4*)&A[(size_t)(k0+kk)*HW + j0 + q];
                float h0=__half2float(__float2half_rn(v.x));
                float h1=__half2float(__float2half_rn(v.y));
                float h2=__half2float(__float2half_rn(v.z));
                float h3=__half2float(__float2half_rn(v.w));
                *(__half2*)&Bhi[kk][q]   = __floats2half2_rn(v.x, v.y);
                *(__half2*)&Bhi[kk][q+2] = __floats2half2_rn(v.z, v.w);
                *(__half2*)&Blo[kk][q]   = __floats2half2_rn(v.x-h0, v.y-h1);
                *(__half2*)&Blo[kk][q+2] = __floats2half2_rn(v.z-h2, v.w-h3);
            }
        }
        __syncthreads();

        #pragma unroll
        for (int kf = 0; kf < 2; kf++) {
            int kk = kf*16;
            uint32_t ah0 = *(const uint32_t*)&Ahi[r0][kk + 2*tig];
            uint32_t ah1 = *(const uint32_t*)&Ahi[r0+8][kk + 2*tig];
            uint32_t ah2 = *(const uint32_t*)&Ahi[r0][kk + 2*tig + 8];
            uint32_t ah3 = *(const uint32_t*)&Ahi[r0+8][kk + 2*tig + 8];
            uint32_t al0 = *(const uint32_t*)&Alo[r0][kk + 2*tig];
            uint32_t al1 = *(const uint32_t*)&Alo[r0+8][kk + 2*tig];
            uint32_t al2 = *(const uint32_t*)&Alo[r0][kk + 2*tig + 8];
            uint32_t al3 = *(const uint32_t*)&Alo[r0+8][kk + 2*tig + 8];
            #pragma unroll
            for (int nb = 0; nb < 2; nb++) {
                uint32_t bh[4], bl[4];
                ldmx4t(bh, &Bhi[kk + b_row][wn*32 + nb*16 + b_col8]);
                ldmx4t(bl, &Blo[kk + b_row][wn*32 + nb*16 + b_col8]);
                mma_f16(acc[nb*2],   ah0, ah1, ah2, ah3, bh[0], bh[1]);
                mma_f16(acc[nb*2],   ah0, ah1, ah2, ah3, bl[0], bl[1]);
                mma_f16(acc[nb*2],   al0, al1, al2, al3, bh[0], bh[1]);
                mma_f16(acc[nb*2+1], ah0, ah1, ah2, ah3, bh[2], bh[3]);
                mma_f16(acc[nb*2+1], ah0, ah1, ah2, ah3, bl[2], bl[3]);
                mma_f16(acc[nb*2+1], al0, al1, al2, al3, bh[2], bh[3]);
            }
        }
    }

    float* G = g_G + ((size_t)(mat*NB + b)) * HW * HW;
    int rg = i0 + wm*16 + g;
    #pragma unroll
    for (int nf = 0; nf < 4; nf++) {
        int col = j0 + wn*32 + nf*8 + tig*2;
        float2 v0; v0.x = acc[nf][0]; v0.y = acc[nf][1];
        float2 v1; v1.x = acc[nf][2]; v1.y = acc[nf][3];
        *(float2*)&G[(size_t)rg*HW + col] = v0;
        *(float2*)&G[(size_t)(rg+8)*HW + col] = v1;
    }
}

// ---------------- K2b: warp-per-row softmax -> S1,S2, S12h (R15 version) ------
__global__ __launch_bounds__(256) void k2b_softmax(float* __restrict__ S1o,
                                                   float* __restrict__ S2o) {
    int b = blockIdx.y;
    int warp = threadIdx.x >> 5, lane = threadIdx.x & 31;
    int i = blockIdx.x * 8 + warp;
    float rr[2][8];
    #pragma unroll
    for (int mat = 0; mat < 2; mat++) {
        const float* row = g_G + (((size_t)(mat*NB + b))*HW + i)*HW + lane*8;
        float4 u0 = *(const float4*)row;
        float4 u1 = *(const float4*)(row + 4);
        float v[8] = {u0.x,u0.y,u0.z,u0.w,u1.x,u1.y,u1.z,u1.w};
        float m = v[0];
        #pragma unroll
        for (int j = 1; j < 8; j++) m = fmaxf(m, v[j]);
        #pragma unroll
        for (int o = 16; o; o >>= 1) m = fmaxf(m, __shfl_xor_sync(0xffffffffu, m, o));
        float s = 0.f;
        #pragma unroll
        for (int j = 0; j < 8; j++) { v[j] = expf(v[j] - m); s += v[j]; }
        #pragma unroll
        for (int o = 16; o; o >>= 1) s += __shfl_xor_sync(0xffffffffu, s, o);
        float inv = 1.f / s;
        #pragma unroll
        for (int j = 0; j < 8; j++) { v[j] *= inv; rr[mat][j] = v[j]; }
        float* dst = (mat == 0 ? S1o : S2o) + ((size_t)b*HW + i)*HW + lane*8;
        float4 w0; w0.x=v[0]; w0.y=v[1]; w0.z=v[2]; w0.w=v[3];
        float4 w1; w1.x=v[4]; w1.y=v[5]; w1.z=v[6]; w1.w=v[7];
        *(float4*)dst = w0;
        *(float4*)(dst + 4) = w1;
    }
    __half2 hs[4];
    #pragma unroll
    for (int j = 0; j < 4; j++)
        hs[j] = __floats2half2_rn(rr[0][2*j] + rr[1][2*j], rr[0][2*j+1] + rr[1][2*j+1]);
    *(uint4*)&g_S12h[((size_t)b*HW + i)*HW + lane*8] = *(uint4*)hs;
}

// ---------------- K34: fused GEMM (fp16 HMMA) + conv + smem residual ----------
__global__ __launch_bounds__(256) void k34_fused(float* __restrict__ out) {
    extern __shared__ char sm_raw[];
    __half* ring = (__half*)sm_raw;              // A stages: 2 x 10240 halves
    __half* Ball = (__half*)(sm_raw + 40960);    // [256][72]
    __half* ms = (__half*)sm_raw;                // [64][264], aliases A ring
    const int ASTG = 10240;
    int b = blockIdx.z;
    int n0 = blockIdx.x * 64;
    const __half* Ag = g_S12h + (size_t)b * HW * HW;
    const __half* Bg = g_C2h + (size_t)b * NC * NP;
    int tid = threadIdx.x;
    int lane = tid & 31;
    int warp = tid >> 5;
    int g = lane >> 2, tig = lane & 3;

    int arow[4], aq[4];
    #pragma unroll
    for (int t = 0; t < 4; t++) { int idx = tid + t*256; arow[t] = idx >> 2; aq[t] = (idx & 3) * 8; }
    int brow = tid >> 3, bq = (tid & 7) * 8;

    int a_row = warp*32 + (lane & 15);
    int a_col8 = (lane >> 4) * 8;
    int b_row = ((lane >> 3) & 1) * 8 + (lane & 7);
    int b_col8 = (lane >> 4) * 8;

    {
        __half* Ad = ring;
        #pragma unroll
        for (int t = 0; t < 4; t++)
            cp_async16(&Ad[arow[t]*40 + aq[t]], &Ag[(size_t)arow[t]*HW + aq[t]]);
        cp_async16(&Ball[brow*72 + bq], &Bg[(size_t)brow*CW + n0 + bq]);
        asm volatile("cp.async.commit_group;");
    }

    float acc[2][8][4];
    #pragma unroll
    for (int mf = 0; mf < 2; mf++)
        #pragma unroll
        for (int nf = 0; nf < 8; nf++)
            #pragma unroll
            for (int r = 0; r < 4; r++) acc[mf][nf][r] = 0.f;

    for (int k0 = 0; k0 < HW; k0 += 32) {
        int stg = (k0 >> 5) & 1;
        if (k0 + 32 < HW) {
            __half* Ad = ring + (stg^1)*ASTG;
            int kn = k0 + 32;
            #pragma unroll
            for (int t = 0; t < 4; t++)
                cp_async16(&Ad[arow[t]*40 + aq[t]], &Ag[(size_t)arow[t]*HW + kn + aq[t]]);
            cp_async16(&Ball[(kn + brow)*72 + bq], &Bg[(size_t)(kn+brow)*CW + n0 + bq]);
            asm volatile("cp.async.commit_group;");
            asm volatile("cp.async.wait_group 1;");
        } else {
            asm volatile("cp.async.wait_group 0;");
        }
        __syncthreads();

        const __half* As = ring + stg*ASTG;
        const __half* Bs = Ball + k0*72;

        #pragma unroll
        for (int kf = 0; kf < 2; kf++) {
            uint32_t a[2][4];
            #pragma unroll
            for (int mf = 0; mf < 2; mf++)
                ldmx4(a[mf], &As[(a_row + mf*16)*40 + kf*16 + a_col8]);
            #pragma unroll
            for (int nb = 0; nb < 4; nb++) {
                uint32_t bb[4];
                ldmx4t(bb, &Bs[(kf*16 + b_row)*72 + nb*16 + b_col8]);
                #pragma unroll
                for (int mf = 0; mf < 2; mf++) {
                    mma_f16(acc[mf][nb*2],   a[mf][0], a[mf][1], a[mf][2], a[mf][3], bb[0], bb[1]);
                    mma_f16(acc[mf][nb*2+1], a[mf][0], a[mf][1], a[mf][2], a[mf][3], bb[2], bb[3]);
                }
            }
        }
        __syncthreads();
    }

    #pragma unroll
    for (int mf = 0; mf < 2; mf++) {
        #pragma unroll
        for (int nf = 0; nf < 8; nf++) {
            int row0 = warp*32 + mf*16 + g;
            int row1 = row0 + 8;
            int col  = nf*8 + tig*2;
            int c0 = row0 >> 2, hh0 = row0 & 3;
            int c1 = row1 >> 2, hh1 = row1 & 3;
            *(__half2*)&ms[c0*264 + hh0*64 + col] = __floats2half2_rn(acc[mf][nf][0], acc[mf][nf][1]);
            *(__half2*)&ms[c1*264 + hh1*64 + col] = __floats2half2_rn(acc[mf][nf][2], acc[mf][nf][3]);
        }
    }
    __syncthreads();

    int wm = warp >> 1;
    int wn = warp & 1;
    int r0 = wm*16 + g;
    int o0 = r0, o1 = r0 + 8;
    float bo0 = g_bOf[o0], bo1 = g_bOf[o1];
    size_t bofs = (size_t)b * NC * NP;

    #pragma unroll
    for (int ph = 0; ph < 2; ph++) {
        int pix_base = ph*128 + wn*64;
        float acc2[8][4];
        #pragma unroll
        for (int nf = 0; nf < 8; nf++)
            #pragma unroll
            for (int r = 0; r < 4; r++) acc2[nf][r] = 0.f;

        #pragma unroll
        for (int kf = 0; kf < 4; kf++) {
            int kk = kf*16;
            uint32_t a0 = *(const uint32_t*)&g_wOh[r0*NC + kk + 2*tig];
            uint32_t a1 = *(const uint32_t*)&g_wOh[(r0+8)*NC + kk + 2*tig];
            uint32_t a2 = *(const uint32_t*)&g_wOh[r0*NC + kk + 2*tig + 8];
            uint32_t a3 = *(const uint32_t*)&g_wOh[(r0+8)*NC + kk + 2*tig + 8];
            #pragma unroll
            for (int nb = 0; nb < 4; nb++) {
                uint32_t bb[4];
                ldmx4t(bb, &ms[(kk + b_row)*264 + pix_base + nb*16 + b_col8]);
                mma_f16(acc2[nb*2],   a0, a1, a2, a3, bb[0], bb[1]);
                mma_f16(acc2[nb*2+1], a0, a1, a2, a3, bb[2], bb[3]);
            }
        }

        #pragma unroll
        for (int nf = 0; nf < 8; nf++) {
            int pix = pix_base + nf*8 + tig*2;
            int hh = pix >> 6, wl = pix & 63;
            size_t off0 = bofs + (size_t)(o0*4 + hh)*CW + n0 + wl;
            size_t off1 = bofs + (size_t)(o1*4 + hh)*CW + n0 + wl;
            float2 c20 = __half22float2(*(const __half2*)&Ball[(o0*4 + hh)*72 + wl]);
            float2 c21 = __half22float2(*(const __half2*)&Ball[(o1*4 + hh)*72 + wl]);
            float2 v0, v1;
            v0.x = c20.x + lrelu(acc2[nf][0] + bo0);
            v0.y = c20.y + lrelu(acc2[nf][1] + bo0);
            v1.x = c21.x + lrelu(acc2[nf][2] + bo1);
            v1.y = c21.y + lrelu(acc2[nf][3] + bo1);
            *(float2*)&out[off0] = v0;
            *(float2*)&out[off1] = v1;
        }
    }
}

#define K34_SMEM 77824

// ---------------- launch --------------------------------------------------------
extern "C" void kernel_launch(void* const* d_in, const int* in_sizes, int n_in,
                              void* d_out, int out_size) {
    const float* x   = (const float*)d_in[0];
    const float* w1  = (const float*)d_in[1];
    const float* b1  = (const float*)d_in[2];
    const float* g1  = (const float*)d_in[3];
    const float* be1 = (const float*)d_in[4];
    const float* m1  = (const float*)d_in[5];
    const float* v1  = (const float*)d_in[6];
    const float* wA  = (const float*)d_in[7];
    const float* bA  = (const float*)d_in[8];
    const float* gA  = (const float*)d_in[9];
    const float* beA = (const float*)d_in[10];
    const float* mA  = (const float*)d_in[11];
    const float* vA  = (const float*)d_in[12];
    const float* wO  = (const float*)d_in[13];
    const float* bO  = (const float*)d_in[14];
    const float* gO  = (const float*)d_in[15];
    const float* beO = (const float*)d_in[16];
    const float* mO  = (const float*)d_in[17];
    const float* vO  = (const float*)d_in[18];

    float* out = (float*)d_out;
    float* S1o = out + (size_t)C2ELEMS;
    float* S2o = S1o + (size_t)SELEMS;

    cudaFuncSetAttribute(k1_c1c2, cudaFuncAttributeMaxDynamicSharedMemorySize, K1_SMEM);
    cudaFuncSetAttribute(k34_fused, cudaFuncAttributeMaxDynamicSharedMemorySize, K34_SMEM);

    k0_fold<<<1, 64>>>(w1,b1,g1,be1,m1,v1, wA,bA,gA,beA,mA,vA, wO,bO,gO,beO,mO,vO);
    k1_c1c2<<<dim3(NP/128, NB), 256, K1_SMEM>>>(x);
    k2a_gram_tc<<<dim3(4, 4, 2*NB), 256>>>();
    k2b_softmax<<<dim3(HW/8, NB), 256>>>(S1o, S2o);
    k34_fused<<<dim3(CW/64, 1, NB), 256, K34_SMEM>>>(out);
}